// round 13
// baseline (speedup 1.0000x reference)
#include <cuda_runtime.h>

#define BB 2
#define NN 512
#define DD 512
#define HH 8
#define EE 128
#define MSPLIT 4
#define MCH (NN / MSPLIT)   // 128 m per block
#define PR 4                // bn rows per prep block, processed in PARALLEL

// Scratch (no cudaMalloc allowed)
__device__ float g_o2[BB * NN * HH];              // 8K floats
__device__ float g_A [(size_t)BB * NN * EE * HH]; // 1M floats = 4 MB

// ---------------------------------------------------------------------------
// Kernel 1 (R10 design, best measured): block handles PR=4 bn rows in parallel.
// ---------------------------------------------------------------------------
__global__ void __launch_bounds__(512) prep_kernel(
    const float* __restrict__ x,    // (B,N,D)
    const float* __restrict__ W12,  // (16,D)
    const float* __restrict__ b12,  // (16,)
    const float* __restrict__ W3)   // (E,64)
{
    const int bn0  = blockIdx.x * PR;
    const int tid  = threadIdx.x;       // 512 threads = 16 warps
    const int warp = tid >> 5;          // = h index in phase A
    const int lane = tid & 31;

    __shared__ float w3s[EE * 65];      // pitch 65 -> conflict-free column reads
    __shared__ float xs[PR * DD];
    __shared__ float o1s[PR][HH];

    for (int idx = tid; idx < EE * 64; idx += 512) {
        int e = idx >> 6, k = idx & 63;
        w3s[e * 65 + k] = W3[idx];
    }
    {
        const float4* xg = reinterpret_cast<const float4*>(x + (size_t)bn0 * DD);
        for (int i = tid; i < PR * DD / 4; i += 512)
            reinterpret_cast<float4*>(xs)[i] = __ldg(xg + i);
    }
    __syncthreads();

    // Phase A: warp h, 4 rows at once (W12 row reused, 4-way ILP)
    {
        float a0 = 0.f, a1 = 0.f, a2 = 0.f, a3 = 0.f;
        const float* w = W12 + warp * DD;
        #pragma unroll 4
        for (int i = lane; i < DD; i += 32) {
            const float wv = __ldg(w + i);
            a0 += wv * xs[0 * DD + i];
            a1 += wv * xs[1 * DD + i];
            a2 += wv * xs[2 * DD + i];
            a3 += wv * xs[3 * DD + i];
        }
        #pragma unroll
        for (int o = 16; o; o >>= 1) {
            a0 += __shfl_xor_sync(0xffffffffu, a0, o);
            a1 += __shfl_xor_sync(0xffffffffu, a1, o);
            a2 += __shfl_xor_sync(0xffffffffu, a2, o);
            a3 += __shfl_xor_sync(0xffffffffu, a3, o);
        }
        if (lane == 0) {
            const float bb = b12[warp];
            float v[PR] = {a0 + bb, a1 + bb, a2 + bb, a3 + bb};
            #pragma unroll
            for (int r = 0; r < PR; r++) {
                if (warp < HH) o1s[r][warp] = v[r];
                else           g_o2[(bn0 + r) * HH + (warp - HH)] = v[r];
            }
        }
    }
    __syncthreads();

    // Phase B: all threads. r = tid/128, e = tid%128.
    {
        const int r = tid >> 7;
        const int e = tid & 127;

        float o1r[HH];
        #pragma unroll
        for (int i = 0; i < HH; i++) o1r[i] = o1s[r][i];   // smem broadcast

        const float* w3 = w3s + e * 65;     // bank=(e+c)%32: conflict-free
        float a[HH];
        #pragma unroll
        for (int j = 0; j < HH; j++) a[j] = 0.f;
        #pragma unroll
        for (int i = 0; i < HH; i++) {
            #pragma unroll
            for (int j = 0; j < HH; j++)
                a[j] += o1r[i] * w3[i * HH + j];
        }
        float* Ao = g_A + ((size_t)(bn0 + r) * EE + e) * HH;
        reinterpret_cast<float4*>(Ao)[0] = make_float4(a[0], a[1], a[2], a[3]);
        reinterpret_cast<float4*>(Ao)[1] = make_float4(a[4], a[5], a[6], a[7]);
    }
}

// ---------------------------------------------------------------------------
// Kernel 2: block per (bn, m-chunk). out[bn,m,e] = b3[e] + sum_j A[bn,e,j]*o2[b,m,j]
// e-QUAD per lane (warp covers all 128 e): per m, 2xLDS.128 + 1xSTG.128 =
// 6 L1-wavefronts per 256B stored (vs 10 for e-pair). Register-dieted to fit
// 5 blocks/SM (<=51 regs): j-split o2 loads keep only 4 o2 floats live.
// ---------------------------------------------------------------------------
__global__ void __launch_bounds__(256, 5) main_kernel(
    const float* __restrict__ b3,   // (E,)
    float* __restrict__ out)        // (B,N,N,E)
{
    const int bn   = blockIdx.x;
    const int b    = bn >> 9;
    const int mc   = blockIdx.y;
    const int tid  = threadIdx.x;      // 256 = 8 warps
    const int warp = tid >> 5;
    const int lane = tid & 31;

    __shared__ float o2s[MCH * HH];    // 4 KB

    const float4* o2g = reinterpret_cast<const float4*>(
        g_o2 + ((size_t)b * NN + (size_t)mc * MCH) * HH);
    for (int i = tid; i < MCH * HH / 4; i += 256)
        reinterpret_cast<float4*>(o2s)[i] = __ldg(o2g + i);

    // lane's e-quad: e = 4*lane -> 32 A regs
    float a0[HH], a1[HH], a2[HH], a3[HH];
    {
        const float4* Ab = reinterpret_cast<const float4*>(
            g_A + ((size_t)bn * EE + 4 * lane) * HH);
        float4 v;
        v = Ab[0]; a0[0]=v.x; a0[1]=v.y; a0[2]=v.z; a0[3]=v.w;
        v = Ab[1]; a0[4]=v.x; a0[5]=v.y; a0[6]=v.z; a0[7]=v.w;
        v = Ab[2]; a1[0]=v.x; a1[1]=v.y; a1[2]=v.z; a1[3]=v.w;
        v = Ab[3]; a1[4]=v.x; a1[5]=v.y; a1[6]=v.z; a1[7]=v.w;
        v = Ab[4]; a2[0]=v.x; a2[1]=v.y; a2[2]=v.z; a2[3]=v.w;
        v = Ab[5]; a2[4]=v.x; a2[5]=v.y; a2[6]=v.z; a2[7]=v.w;
        v = Ab[6]; a3[0]=v.x; a3[1]=v.y; a3[2]=v.z; a3[3]=v.w;
        v = Ab[7]; a3[4]=v.x; a3[5]=v.y; a3[6]=v.z; a3[7]=v.w;
    }
    const float4 bv = reinterpret_cast<const float4*>(b3)[lane];

    __syncthreads();

    // out as float4: row (bn,m) has EE/4 = 32 float4; lane owns slot lane.
    float4* op = reinterpret_cast<float4*>(out)
               + ((size_t)bn * NN + (size_t)mc * MCH + warp) * (EE / 4) + lane;
    const float4* o2v = reinterpret_cast<const float4*>(o2s) + warp * 2;

    #pragma unroll 4
    for (int it = 0; it < MCH / 8; ++it) {   // m = warp + 8*it
        float4 acc = bv;
        {   // j = 0..3
            const float4 p = o2v[0];
            acc.x += a0[0]*p.x;  acc.y += a1[0]*p.x;  acc.z += a2[0]*p.x;  acc.w += a3[0]*p.x;
            acc.x += a0[1]*p.y;  acc.y += a1[1]*p.y;  acc.z += a2[1]*p.y;  acc.w += a3[1]*p.y;
            acc.x += a0[2]*p.z;  acc.y += a1[2]*p.z;  acc.z += a2[2]*p.z;  acc.w += a3[2]*p.z;
            acc.x += a0[3]*p.w;  acc.y += a1[3]*p.w;  acc.z += a2[3]*p.w;  acc.w += a3[3]*p.w;
        }
        {   // j = 4..7
            const float4 q = o2v[1];
            acc.x += a0[4]*q.x;  acc.y += a1[4]*q.x;  acc.z += a2[4]*q.x;  acc.w += a3[4]*q.x;
            acc.x += a0[5]*q.y;  acc.y += a1[5]*q.y;  acc.z += a2[5]*q.y;  acc.w += a3[5]*q.y;
            acc.x += a0[6]*q.z;  acc.y += a1[6]*q.z;  acc.z += a2[6]*q.z;  acc.w += a3[6]*q.z;
            acc.x += a0[7]*q.w;  acc.y += a1[7]*q.w;  acc.z += a2[7]*q.w;  acc.w += a3[7]*q.w;
        }
        __stcs(op, acc);
        op  += 8 * (EE / 4);   // next m (stride 8)
        o2v += 8 * 2;
    }
}

extern "C" void kernel_launch(void* const* d_in, const int* in_sizes, int n_in,
                              void* d_out, int out_size)
{
    const float* x   = (const float*)d_in[0];
    const float* W12 = (const float*)d_in[1];
    const float* b12 = (const float*)d_in[2];
    const float* W3  = (const float*)d_in[3];
    const float* b3  = (const float*)d_in[4];
    float* out = (float*)d_out;

    prep_kernel<<<BB * NN / PR, 512>>>(x, W12, b12, W3);
    main_kernel<<<dim3(BB * NN, MSPLIT), 256>>>(b3, out);
}

// round 14
// speedup vs baseline: 1.6306x; 1.6306x over previous
#include <cuda_runtime.h>

#define BB 2
#define NN 512
#define DD 512
#define HH 8
#define EE 128
#define MSPLIT 4
#define MCH (NN / MSPLIT)   // 128 m per block
#define PR 4                // bn rows per o12 block

// Scratch (no cudaMalloc allowed): full o12 activations (o1 | o2), 16 per row
__device__ float g_o12[BB * NN * 16];

// ---------------------------------------------------------------------------
// Kernel 1: o12 = x @ W12^T + b12 only (A is computed inside main now).
// Block handles PR=4 bn rows; warp h computes o12[bn0+r, h] for r=0..3.
// ---------------------------------------------------------------------------
__global__ void __launch_bounds__(512) o12_kernel(
    const float* __restrict__ x,    // (B,N,D)
    const float* __restrict__ W12,  // (16,D)
    const float* __restrict__ b12)  // (16,)
{
    const int bn0  = blockIdx.x * PR;
    const int tid  = threadIdx.x;       // 512 threads = 16 warps
    const int warp = tid >> 5;          // h index
    const int lane = tid & 31;

    __shared__ float xs[PR * DD];       // 8 KB

    {
        const float4* xg = reinterpret_cast<const float4*>(x + (size_t)bn0 * DD);
        for (int i = tid; i < PR * DD / 4; i += 512)
            reinterpret_cast<float4*>(xs)[i] = __ldg(xg + i);
    }
    __syncthreads();

    float a0 = 0.f, a1 = 0.f, a2 = 0.f, a3 = 0.f;
    const float* w = W12 + warp * DD;
    #pragma unroll 4
    for (int i = lane; i < DD; i += 32) {
        const float wv = __ldg(w + i);
        a0 += wv * xs[0 * DD + i];
        a1 += wv * xs[1 * DD + i];
        a2 += wv * xs[2 * DD + i];
        a3 += wv * xs[3 * DD + i];
    }
    #pragma unroll
    for (int o = 16; o; o >>= 1) {
        a0 += __shfl_xor_sync(0xffffffffu, a0, o);
        a1 += __shfl_xor_sync(0xffffffffu, a1, o);
        a2 += __shfl_xor_sync(0xffffffffu, a2, o);
        a3 += __shfl_xor_sync(0xffffffffu, a3, o);
    }
    if (lane == 0) {
        const float bb = b12[warp];
        g_o12[(bn0 + 0) * 16 + warp] = a0 + bb;
        g_o12[(bn0 + 1) * 16 + warp] = a1 + bb;
        g_o12[(bn0 + 2) * 16 + warp] = a2 + bb;
        g_o12[(bn0 + 3) * 16 + warp] = a3 + bb;
    }
}

// ---------------------------------------------------------------------------
// Kernel 2: block per (bn, m-chunk).
//   Prologue: compute A[e][j] = sum_i o1[bn,i] * W3[e, i*8+j] into smem
//             (j-major layout: As[j*EE+e] -> conflict-free STS and LDS.64).
//   Loop (R8 design): e-PAIR per lane, 2xLDS.128 + 16 FFMA pairs + STG.64.
// ---------------------------------------------------------------------------
__global__ void __launch_bounds__(256, 6) main_kernel(
    const float* __restrict__ W3,   // (E,64)
    const float* __restrict__ b3,   // (E,)
    float* __restrict__ out)        // (B,N,N,E)
{
    const int bn   = blockIdx.x;
    const int b    = bn >> 9;
    const int mc   = blockIdx.y;
    const int tid  = threadIdx.x;      // 256 = 8 warps
    const int warp = tid >> 5;
    const int lane = tid & 31;

    __shared__ float o2s[MCH * HH];    // 4 KB
    __shared__ float As[HH * EE];      // 4 KB, j-major: As[j*EE + e]

    // stage o2 slice: o2s[row*8+j] = o12[b*NN + mc*MCH + row][8+j]
    for (int i = tid; i < MCH * 2; i += 256) {
        const int row = i >> 1, h = i & 1;
        reinterpret_cast<float4*>(o2s)[row * 2 + h] =
            __ldg(reinterpret_cast<const float4*>(
                g_o12 + ((size_t)(b * NN) + mc * MCH + row) * 16 + 8 + h * 4));
    }

    // compute A into smem: thread t -> e = t>>1, j-half = (t&1)*4
    {
        const int e  = tid >> 1;
        const int jh = (tid & 1) * 4;
        float4 acc = make_float4(0.f, 0.f, 0.f, 0.f);
        const float* o1 = g_o12 + (size_t)bn * 16;
        #pragma unroll
        for (int i = 0; i < HH; i++) {
            const float o1v = __ldg(o1 + i);
            const float4 wv = __ldg(reinterpret_cast<const float4*>(
                W3 + e * (HH * HH) + i * HH + jh));
            acc.x += o1v * wv.x;
            acc.y += o1v * wv.y;
            acc.z += o1v * wv.z;
            acc.w += o1v * wv.w;
        }
        As[(jh + 0) * EE + e] = acc.x;
        As[(jh + 1) * EE + e] = acc.y;
        As[(jh + 2) * EE + e] = acc.z;
        As[(jh + 3) * EE + e] = acc.w;
    }
    __syncthreads();

    // lane's e-pair: e = 64*(warp&1) + 2*lane -> 16 A regs (conflict-free LDS.64)
    const int ebase = ((warp & 1) << 6) + (lane << 1);
    float a0[HH], a1[HH];
    #pragma unroll
    for (int j = 0; j < HH; j++) {
        const float2 v = *reinterpret_cast<const float2*>(As + j * EE + ebase);
        a0[j] = v.x; a1[j] = v.y;
    }
    const float2 bv = reinterpret_cast<const float2*>(b3)[ebase >> 1];

    // out as float2: row (bn,m) has EE/2 = 64 float2; lane owns slot ebase/2
    const int m0 = warp >> 1;          // 0..3
    float2* op = reinterpret_cast<float2*>(out)
               + ((size_t)bn * NN + (size_t)mc * MCH + m0) * (EE / 2) + (ebase >> 1);
    const float4* o2v = reinterpret_cast<const float4*>(o2s) + m0 * 2;

    #pragma unroll 8
    for (int it = 0; it < MCH / 4; ++it) {   // m = m0 + 4*it
        const float4 p  = o2v[0];
        const float4 qv = o2v[1];

        float ax = bv.x, ay = bv.y;
        ax += a0[0]*p.x;  ay += a1[0]*p.x;
        ax += a0[1]*p.y;  ay += a1[1]*p.y;
        ax += a0[2]*p.z;  ay += a1[2]*p.z;
        ax += a0[3]*p.w;  ay += a1[3]*p.w;
        ax += a0[4]*qv.x; ay += a1[4]*qv.x;
        ax += a0[5]*qv.y; ay += a1[5]*qv.y;
        ax += a0[6]*qv.z; ay += a1[6]*qv.z;
        ax += a0[7]*qv.w; ay += a1[7]*qv.w;

        __stcs(op, make_float2(ax, ay));
        op  += 4 * (EE / 2);   // next m (stride 4)
        o2v += 4 * 2;
    }
}

extern "C" void kernel_launch(void* const* d_in, const int* in_sizes, int n_in,
                              void* d_out, int out_size)
{
    const float* x   = (const float*)d_in[0];
    const float* W12 = (const float*)d_in[1];
    const float* b12 = (const float*)d_in[2];
    const float* W3  = (const float*)d_in[3];
    const float* b3  = (const float*)d_in[4];
    float* out = (float*)d_out;

    o12_kernel<<<BB * NN / PR, 512>>>(x, W12, b12);
    main_kernel<<<dim3(BB * NN, MSPLIT), 256>>>(W3, b3, out);
}

// round 15
// speedup vs baseline: 1.6373x; 1.0041x over previous
#include <cuda_runtime.h>

#define BB 2
#define NN 512
#define DD 512
#define HH 8
#define EE 128
#define MSPLIT 4
#define MCH (NN / MSPLIT)   // 128 m per block
#define PR 4                // bn rows per block (o12 and A kernels)

// Scratch (no cudaMalloc allowed)
__device__ float g_o12[BB * NN * 16];             // o1 | o2 per row
__device__ float g_A [(size_t)BB * NN * EE * HH]; // 1M floats = 4 MB

// ---------------------------------------------------------------------------
// Kernel 1: o12 = x @ W12^T + b12.  Block handles PR=4 bn rows;
// warp h computes o12[bn0+r, h] for r=0..3 (4-way ILP dots).
// ---------------------------------------------------------------------------
__global__ void __launch_bounds__(512) o12_kernel(
    const float* __restrict__ x,    // (B,N,D)
    const float* __restrict__ W12,  // (16,D)
    const float* __restrict__ b12)  // (16,)
{
    const int bn0  = blockIdx.x * PR;
    const int tid  = threadIdx.x;       // 512 threads = 16 warps
    const int warp = tid >> 5;          // h index
    const int lane = tid & 31;

    __shared__ float xs[PR * DD];       // 8 KB

    {
        const float4* xg = reinterpret_cast<const float4*>(x + (size_t)bn0 * DD);
        for (int i = tid; i < PR * DD / 4; i += 512)
            reinterpret_cast<float4*>(xs)[i] = __ldg(xg + i);
    }
    __syncthreads();

    float a0 = 0.f, a1 = 0.f, a2 = 0.f, a3 = 0.f;
    const float* w = W12 + warp * DD;
    #pragma unroll 4
    for (int i = lane; i < DD; i += 32) {
        const float wv = __ldg(w + i);
        a0 += wv * xs[0 * DD + i];
        a1 += wv * xs[1 * DD + i];
        a2 += wv * xs[2 * DD + i];
        a3 += wv * xs[3 * DD + i];
    }
    #pragma unroll
    for (int o = 16; o; o >>= 1) {
        a0 += __shfl_xor_sync(0xffffffffu, a0, o);
        a1 += __shfl_xor_sync(0xffffffffu, a1, o);
        a2 += __shfl_xor_sync(0xffffffffu, a2, o);
        a3 += __shfl_xor_sync(0xffffffffu, a3, o);
    }
    if (lane == 0) {
        const float bb = b12[warp];
        g_o12[(bn0 + 0) * 16 + warp] = a0 + bb;
        g_o12[(bn0 + 1) * 16 + warp] = a1 + bb;
        g_o12[(bn0 + 2) * 16 + warp] = a2 + bb;
        g_o12[(bn0 + 3) * 16 + warp] = a3 + bb;
    }
}

// ---------------------------------------------------------------------------
// Kernel 2: A[bn, e, j] = sum_i o1[bn, i] * W3[e, i*8+j].
// Block handles PR=4 bn rows: stage W3 once (padded pitch 65 -> conflict-free
// column reads), then thread (r = tid>>7, e = tid&127) does 64 FMA.
// ---------------------------------------------------------------------------
__global__ void __launch_bounds__(512) a_kernel(
    const float* __restrict__ W3)   // (E,64)
{
    const int bn0  = blockIdx.x * PR;
    const int tid  = threadIdx.x;       // 512 threads

    __shared__ float w3s[EE * 65];      // 33 KB

    for (int idx = tid; idx < EE * 64; idx += 512) {
        int e = idx >> 6, k = idx & 63;
        w3s[e * 65 + k] = W3[idx];
    }
    __syncthreads();

    const int r = tid >> 7;             // 0..3
    const int e = tid & 127;

    float o1r[HH];
    {
        const float* o1 = g_o12 + (size_t)(bn0 + r) * 16;
        #pragma unroll
        for (int i = 0; i < HH; i++) o1r[i] = __ldg(o1 + i);   // L1 broadcast
    }

    const float* w3 = w3s + e * 65;     // bank=(e+c)%32: conflict-free
    float a[HH];
    #pragma unroll
    for (int j = 0; j < HH; j++) a[j] = 0.f;
    #pragma unroll
    for (int i = 0; i < HH; i++) {
        #pragma unroll
        for (int j = 0; j < HH; j++)
            a[j] += o1r[i] * w3[i * HH + j];
    }
    float* Ao = g_A + ((size_t)(bn0 + r) * EE + e) * HH;
    reinterpret_cast<float4*>(Ao)[0] = make_float4(a[0], a[1], a[2], a[3]);
    reinterpret_cast<float4*>(Ao)[1] = make_float4(a[4], a[5], a[6], a[7]);
}

// ---------------------------------------------------------------------------
// Kernel 3 (R8's proven loop, byte-for-byte): block per (bn, m-chunk).
// out[bn,m,e] = b3[e] + sum_j A[bn,e,j]*o2[b,m,j]
// e-PAIR per lane (16 A regs); warp-pairs split the e-range; scalar FFMA;
// coalesced 256B streaming STG.64 per warp per m. 40 regs -> 75% occ cap.
// ---------------------------------------------------------------------------
__global__ void __launch_bounds__(256, 6) main_kernel(
    const float* __restrict__ b3,   // (E,)
    float* __restrict__ out)        // (B,N,N,E)
{
    const int bn   = blockIdx.x;
    const int b    = bn >> 9;
    const int mc   = blockIdx.y;
    const int tid  = threadIdx.x;      // 256 = 8 warps
    const int warp = tid >> 5;
    const int lane = tid & 31;

    __shared__ float o2s[MCH * HH];    // 4 KB

    // o2 slice from g_o12 (upper 8 floats of each 16-float row)
    for (int i = tid; i < MCH * 2; i += 256) {
        const int row = i >> 1, h = i & 1;
        reinterpret_cast<float4*>(o2s)[row * 2 + h] =
            __ldg(reinterpret_cast<const float4*>(
                g_o12 + ((size_t)(b * NN) + mc * MCH + row) * 16 + 8 + h * 4));
    }

    // lane's e-pair: e = 64*(warp&1) + 2*lane  -> 16 A regs
    const int ebase = ((warp & 1) << 6) + (lane << 1);
    float a0[HH], a1[HH];
    {
        const float4* Ab = reinterpret_cast<const float4*>(
            g_A + ((size_t)bn * EE + ebase) * HH);
        float4 v0 = Ab[0], v1 = Ab[1], v2 = Ab[2], v3 = Ab[3];
        a0[0]=v0.x; a0[1]=v0.y; a0[2]=v0.z; a0[3]=v0.w;
        a0[4]=v1.x; a0[5]=v1.y; a0[6]=v1.z; a0[7]=v1.w;
        a1[0]=v2.x; a1[1]=v2.y; a1[2]=v2.z; a1[3]=v2.w;
        a1[4]=v3.x; a1[5]=v3.y; a1[6]=v3.z; a1[7]=v3.w;
    }
    const float2 bv = reinterpret_cast<const float2*>(b3)[ebase >> 1];

    __syncthreads();

    // out as float2: row (bn,m) has EE/2 = 64 float2; lane owns slot ebase/2
    float2* outp = reinterpret_cast<float2*>(out)
                 + ((size_t)bn * NN + (size_t)mc * MCH) * (EE / 2) + (ebase >> 1);

    for (int m = (warp >> 1); m < MCH; m += 4) {
        const float4 p  = reinterpret_cast<const float4*>(o2s + m * HH)[0];
        const float4 qv = reinterpret_cast<const float4*>(o2s + m * HH)[1];
        const float o2r[HH] = {p.x, p.y, p.z, p.w, qv.x, qv.y, qv.z, qv.w};

        float ax = bv.x, ay = bv.y;
        #pragma unroll
        for (int j = 0; j < HH; j++) {
            ax += a0[j] * o2r[j];
            ay += a1[j] * o2r[j];
        }
        __stcs(outp + (size_t)m * (EE / 2), make_float2(ax, ay));
    }
}

extern "C" void kernel_launch(void* const* d_in, const int* in_sizes, int n_in,
                              void* d_out, int out_size)
{
    const float* x   = (const float*)d_in[0];
    const float* W12 = (const float*)d_in[1];
    const float* b12 = (const float*)d_in[2];
    const float* W3  = (const float*)d_in[3];
    const float* b3  = (const float*)d_in[4];
    float* out = (float*)d_out;

    o12_kernel<<<BB * NN / PR, 512>>>(x, W12, b12);
    a_kernel  <<<BB * NN / PR, 512>>>(W3);
    main_kernel<<<dim3(BB * NN, MSPLIT), 256>>>(b3, out);
}